// round 2
// baseline (speedup 1.0000x reference)
#include <cuda_runtime.h>
#include <cuda_bf16.h>

#define NROWS 8192
#define NCOLS 32000
#define NVEC  (NCOLS / 4)   // 8000 float4 per row
#define BLK   256

// ex2.approx.f32 : single MUFU EX2, ~2^-22 rel err (far under 1e-3 budget)
__device__ __forceinline__ float ex2(float x) {
    float y;
    asm("ex2.approx.f32 %0, %1;" : "=f"(y) : "f"(x));
    return y;
}

__global__ void zero_out_kernel(float* out) { *out = 0.0f; }

__global__ __launch_bounds__(BLK)
void arcface_loss_kernel(const float* __restrict__ pred,
                         const int* __restrict__ target,
                         float* __restrict__ out) {
    // constants (double-accurate, truncated to f32)
    const float S     = 30.0f;
    const float K     = 30.0f * 1.4426950408889634f;   // S * log2(e): exp(S*c) = 2^(K*c)
    const float COSM  = 0.87758256189037271f;          // cos(0.5)
    const float SINM  = 0.47942553860420301f;          // sin(0.5)
    const float MM    = 0.23971276930210150f;          // sin(pi-0.5)*0.5
    const float TH    = -0.87758256189037271f;         // cos(pi-0.5)

    const int row = blockIdx.x;
    const float4* __restrict__ p4 =
        reinterpret_cast<const float4*>(pred + (size_t)row * NCOLS);

    // ---- hot loop: uniform streaming sum of exp(S * clip(p)) ----
    float sum = 0.0f;
    #pragma unroll 4
    for (int i = threadIdx.x; i < NVEC; i += BLK) {
        float4 v = p4[i];
        sum += ex2(K * fminf(1.0f, fmaxf(-1.0f, v.x)));
        sum += ex2(K * fminf(1.0f, fmaxf(-1.0f, v.y)));
        sum += ex2(K * fminf(1.0f, fmaxf(-1.0f, v.z)));
        sum += ex2(K * fminf(1.0f, fmaxf(-1.0f, v.w)));
    }

    // ---- block reduction ----
    __shared__ float warp_sums[BLK / 32];
    #pragma unroll
    for (int o = 16; o > 0; o >>= 1)
        sum += __shfl_xor_sync(0xffffffffu, sum, o);
    const int wid = threadIdx.x >> 5;
    const int lid = threadIdx.x & 31;
    if (lid == 0) warp_sums[wid] = sum;
    __syncthreads();

    if (threadIdx.x == 0) {
        float tot = 0.0f;
        #pragma unroll
        for (int w = 0; w < BLK / 32; w++) tot += warp_sums[w];

        // ---- target-column correction (scalar, per row) ----
        const int tgt = target[row];
        const float ct = fminf(1.0f, fmaxf(-1.0f,
                          pred[(size_t)row * NCOLS + tgt]));
        // cos(acos(ct) + M) = ct*cosM - sqrt(1-ct^2)*sinM  (exact identity)
        const float sm = sqrtf(fmaxf(0.0f, 1.0f - ct * ct));
        float tm = ct * COSM - sm * SINM;
        tm = (ct > TH) ? tm : (ct - MM);

        // replace exp(S*ct) by exp(S*tm) in the row sum
        tot += ex2(K * tm) - ex2(K * ct);

        const float loss = logf(tot) - S * tm;
        atomicAdd(out, loss * (1.0f / (float)NROWS));
    }
}

extern "C" void kernel_launch(void* const* d_in, const int* in_sizes, int n_in,
                              void* d_out, int out_size) {
    const float* pred   = (const float*)d_in[0];
    const int*   target = (const int*)d_in[1];
    float*       out    = (float*)d_out;

    zero_out_kernel<<<1, 1>>>(out);
    arcface_loss_kernel<<<NROWS, BLK>>>(pred, target, out);
}